// round 17
// baseline (speedup 1.0000x reference)
#include <cuda_runtime.h>
#include <cuda_fp16.h>

#define N_NODES 100000
#define N_EDGES 1600000
#define DIM 128
#define EDIM 16
#define NBLK 98             // ceil(100000/1024)

typedef unsigned long long u64;

// f32x2 packed math (sm_103a; ptxas never auto-fuses these)
#define FMA2(d, a, b, c) asm("fma.rn.f32x2 %0, %1, %2, %3;" : "=l"(d) : "l"(a), "l"(b), "l"(c))
#define ADD2(d, a, b)    asm("add.rn.f32x2 %0, %1, %2;"     : "=l"(d) : "l"(a), "l"(b))
#define PACK2(d, lo, hi) asm("mov.b64 %0, {%1, %2};" : "=l"(d) : "r"(__float_as_uint(lo)), "r"(__float_as_uint(hi)))
#define UNPK2(lo, hi, v) do { unsigned _ulo, _uhi; asm("mov.b64 {%0, %1}, %2;" : "=r"(_ulo), "=r"(_uhi) : "l"(v)); lo = __uint_as_float(_ulo); hi = __uint_as_float(_uhi); } while (0)

// ---------------- static scratch (no allocations allowed) ----------------
__device__ __align__(16) float    g_h[N_NODES * DIM];    // node features between layers
__device__ __align__(16) __half   g_glh[N_NODES * DIM];  // x @ Wl + bl (fp16, 25MB)
__device__ __align__(16) float    g_gr[N_NODES * DIM];   // x @ Wr + br
__device__ __align__(16) unsigned g_eacsr[(size_t)N_EDGES * EDIM]; // EA half2(v,v), CSR order
__device__ __align__(16) __half   g_ee[(size_t)N_EDGES * DIM];     // edge transform, CSR order
__device__ int   g_cnt[N_NODES];                      // zero at load; re-zeroed by scan1
__device__ int   g_off[N_NODES + 1];
__device__ int   g_cursor[N_NODES];
__device__ int   g_bsum[128];
__device__ int   g_srcarr[N_EDGES];                   // src node per CSR position
__device__ int   g_epos[N_EDGES];                     // edge -> CSR position
__device__ float g_stats[2 * DIM];                    // sum | sumsq (re-zeroed by bn_finalize)
__device__ float g_bnp[2 * DIM];                      // scale | shift

// ---------------- CSR build ----------------
// edge_index is INT32 (JAX x64-disabled downcast)
__global__ void k_hist(const int* __restrict__ ei, int* __restrict__ cnt) {
    int e = blockIdx.x * blockDim.x + threadIdx.x;
    if (e < N_EDGES) atomicAdd(&cnt[ei[N_EDGES + e]], 1);
}

__global__ void k_scan1(int* __restrict__ cnt, int* __restrict__ off,
                        int* __restrict__ bsum) {
    __shared__ int s[1024];
    int tid = threadIdx.x;
    int i = blockIdx.x * 1024 + tid;
    int v = (i < N_NODES) ? cnt[i] : 0;
    if (i < N_NODES) cnt[i] = 0;           // re-zero for next call
    s[tid] = v; __syncthreads();
    for (int d = 1; d < 1024; d <<= 1) {
        int t = (tid >= d) ? s[tid - d] : 0;
        __syncthreads();
        s[tid] += t;
        __syncthreads();
    }
    if (i < N_NODES) off[i] = s[tid] - v;   // exclusive within block
    if (tid == 1023) bsum[blockIdx.x] = s[1023];
}

__global__ void k_scan23(int* __restrict__ off, const int* __restrict__ bsum,
                         int* __restrict__ cursor) {
    __shared__ int sp[NBLK];
    int tid = threadIdx.x;
    if (tid == 0) {
        int acc = 0;
        for (int b = 0; b < NBLK; b++) { sp[b] = acc; acc += bsum[b]; }
    }
    __syncthreads();
    int i = blockIdx.x * blockDim.x + tid;
    if (i < N_NODES) {
        int o = off[i] + sp[i >> 10];
        off[i] = o;
        cursor[i] = o;
    }
    if (i == 0) off[N_NODES] = N_EDGES;
}

__global__ void k_scatter(const int* __restrict__ ei, int* __restrict__ cursor,
                          int* __restrict__ srcarr, int* __restrict__ epos) {
    int e = blockIdx.x * blockDim.x + threadIdx.x;
    if (e < N_EDGES) {
        int src = ei[e];
        int dst = ei[N_EDGES + e];
        int pos = atomicAdd(&cursor[dst], 1);
        srcarr[pos] = src;
        epos[e] = pos;
    }
}

// ---------------- one-time permute: EA (f32) -> half2(v,v) rows in CSR order -
__global__ __launch_bounds__(256) void k_permute(
    const float* __restrict__ EA, const int* __restrict__ epos,
    unsigned* __restrict__ eacsr)
{
    int e = blockIdx.x * 256 + threadIdx.x;
    int pos = epos[e];
    const float4* src = (const float4*)(EA + (size_t)e * EDIM);
    uint4* dst = (uint4*)(eacsr + (size_t)pos * EDIM);
#pragma unroll
    for (int i = 0; i < 4; i++) {
        float4 v = src[i];
        __half2 h0 = __float2half2_rn(v.x);
        __half2 h1 = __float2half2_rn(v.y);
        __half2 h2 = __float2half2_rn(v.z);
        __half2 h3 = __float2half2_rn(v.w);
        uint4 o;
        o.x = *reinterpret_cast<unsigned*>(&h0);
        o.y = *reinterpret_cast<unsigned*>(&h1);
        o.z = *reinterpret_cast<unsigned*>(&h2);
        o.w = *reinterpret_cast<unsigned*>(&h3);
        dst[i] = o;
    }
}

// ---------------- dual node GEMM (column-pair f32x2; zero PACK2 in loop) -----
// Thread owns output columns (2cp, 2cp+1) for 8 nodes. Weight pair is a
// natural LDG.64; x is pre-duplicated (v,v) in smem (18-u64 padded rows).
// Per-element k-order identical to previous version -> bit-identical output.
#define SX2S 18
__global__ __launch_bounds__(128) void k_gemm_dual(
    const float* __restrict__ h, int applyBN, const float* __restrict__ bnp,
    const float* __restrict__ Wl, const float* __restrict__ bl,
    const float* __restrict__ Wr, const float* __restrict__ br,
    __half* __restrict__ glh, float* __restrict__ gr)
{
    __shared__ __align__(16) u64 sx2[128 * SX2S];
    __shared__ float sSc[DIM], sSh[DIM];
    int tid = threadIdx.x;
    sSc[tid] = bnp[tid];
    sSh[tid] = bnp[DIM + tid];
    __syncthreads();
    int n0 = blockIdx.x * 16;
    {
        int k = tid;
        float sc = sSc[k], sh = sSh[k];
#pragma unroll
        for (int it = 0; it < 16; it++) {
            float v = h[(size_t)(n0 + it) * DIM + k];
            if (applyBN) {
                v = v * sc + sh;
                v = v > 0.f ? v : 0.02f * v;
            }
            u64 d; PACK2(d, v, v);
            sx2[k * SX2S + it] = d;
        }
    }
    __syncthreads();
    int cp = tid & 63;
    int ng = tid >> 6;
    int c0 = cp * 2;
    u64 accl[8], accr[8];
    u64 zz; PACK2(zz, 0.f, 0.f);
#pragma unroll
    for (int p = 0; p < 8; p++) { accl[p] = zz; accr[p] = zz; }
#pragma unroll 4
    for (int k = 0; k < 128; k++) {
        u64 wl2 = *(const u64*)(Wl + k * DIM + c0);   // natural pair, no PACK2
        u64 wr2 = *(const u64*)(Wr + k * DIM + c0);
        const ulonglong2* xp = (const ulonglong2*)(sx2 + k * SX2S + ng * 8);
#pragma unroll
        for (int p = 0; p < 4; p++) {
            ulonglong2 xv = xp[p];          // LDS.128 broadcast
            FMA2(accl[2 * p],     xv.x, wl2, accl[2 * p]);
            FMA2(accr[2 * p],     xv.x, wr2, accr[2 * p]);
            FMA2(accl[2 * p + 1], xv.y, wl2, accl[2 * p + 1]);
            FMA2(accr[2 * p + 1], xv.y, wr2, accr[2 * p + 1]);
        }
    }
    float blv0 = bl[c0], blv1 = bl[c0 + 1];
    float brv0 = br[c0], brv1 = br[c0 + 1];
#pragma unroll
    for (int p = 0; p < 8; p++) {
        int n = n0 + ng * 8 + p;
        float l0, l1, r0, r1;
        UNPK2(l0, l1, accl[p]);
        UNPK2(r0, r1, accr[p]);
        __half2 hh = __floats2half2_rn(l0 + blv0, l1 + blv1);
        *(unsigned*)(glh + (size_t)n * DIM + c0) = *reinterpret_cast<unsigned*>(&hh);
        float2 rr; rr.x = r0 + brv0; rr.y = r1 + brv1;
        *(float2*)(gr + (size_t)n * DIM + c0) = rr;
    }
}

// ---------------- final projection (column-pair f32x2) ----------------
__global__ __launch_bounds__(128) void k_gemm_final(
    const float* __restrict__ h, const float* __restrict__ bnp,
    const float* __restrict__ Wf, const float* __restrict__ bf,
    float* __restrict__ out)
{
    __shared__ __align__(16) u64 sx2[128 * SX2S];
    __shared__ float sSc[DIM], sSh[DIM];
    int tid = threadIdx.x;
    sSc[tid] = bnp[tid];
    sSh[tid] = bnp[DIM + tid];
    __syncthreads();
    int n0 = blockIdx.x * 16;
    {
        int k = tid;
        float sc = sSc[k], sh = sSh[k];
#pragma unroll
        for (int it = 0; it < 16; it++) {
            float v = h[(size_t)(n0 + it) * DIM + k];
            v = v * sc + sh;
            v = v > 0.f ? v : 0.02f * v;
            u64 d; PACK2(d, v, v);
            sx2[k * SX2S + it] = d;
        }
    }
    __syncthreads();
    int cp = tid & 63;
    int ng = tid >> 6;
    int c0 = cp * 2;
    u64 acc[8];
    u64 zz; PACK2(zz, 0.f, 0.f);
#pragma unroll
    for (int p = 0; p < 8; p++) acc[p] = zz;
#pragma unroll 4
    for (int k = 0; k < 128; k++) {
        u64 wf2 = *(const u64*)(Wf + k * DIM + c0);
        const ulonglong2* xp = (const ulonglong2*)(sx2 + k * SX2S + ng * 8);
#pragma unroll
        for (int p = 0; p < 4; p++) {
            ulonglong2 xv = xp[p];
            FMA2(acc[2 * p],     xv.x, wf2, acc[2 * p]);
            FMA2(acc[2 * p + 1], xv.y, wf2, acc[2 * p + 1]);
        }
    }
    float bfv0 = bf[c0], bfv1 = bf[c0 + 1];
#pragma unroll
    for (int p = 0; p < 8; p++) {
        int n = n0 + ng * 8 + p;
        float o0, o1;
        UNPK2(o0, o1, acc[p]);
        float2 oo; oo.x = o0 + bfv0; oo.y = o1 + bfv1;
        *(float2*)(out + (size_t)n * DIM + c0) = oo;
    }
}

// ---------------- edge transform GEMM (all-fp16, CSR-ordered I/O) ------------
__global__ __launch_bounds__(256) void k_ee(
    const unsigned* __restrict__ eacsr, const float* __restrict__ We,
    __half* __restrict__ ee)
{
    __shared__ __align__(16) uint4 sbuf[256 * 4];   // 256 edges x 64B = 16KB
    int tid = threadIdx.x;
    int lane = tid & 31;
    int wrp = tid >> 5;
    int jb = lane * 4;

    __half2 we01h[16], we23h[16];
#pragma unroll
    for (int kk = 0; kk < 16; kk++) {
        float4 wv = *(const float4*)(We + kk * DIM + jb);
        we01h[kk] = __floats2half2_rn(wv.x, wv.y);
        we23h[kk] = __floats2half2_rn(wv.z, wv.w);
    }

    size_t ebase = (size_t)blockIdx.x * 256;
    const uint4* gp = (const uint4*)(eacsr + ebase * EDIM);
#pragma unroll
    for (int i = 0; i < 4; i++)
        sbuf[tid + i * 256] = gp[tid + i * 256];    // coalesced, MLP=4/thread
    __syncthreads();

    int le0 = wrp * 32;
#pragma unroll 2
    for (int q = 0; q < 32; q++) {
        int le = le0 + q;
        uint4 ua = sbuf[le * 4 + 0];                // LDS.128 broadcast
        uint4 ub = sbuf[le * 4 + 1];
        uint4 uc = sbuf[le * 4 + 2];
        uint4 ud = sbuf[le * 4 + 3];
        __half2 z = __float2half2_rn(0.f);
        __half2 a01 = z, b01 = z, a23 = z, b23 = z;
#define EE_STEP(u, k0)                                                        \
        {                                                                     \
            __half2 s0 = *reinterpret_cast<__half2*>(&(u).x);                 \
            __half2 s1 = *reinterpret_cast<__half2*>(&(u).y);                 \
            __half2 s2 = *reinterpret_cast<__half2*>(&(u).z);                 \
            __half2 s3 = *reinterpret_cast<__half2*>(&(u).w);                 \
            a01 = __hfma2(s0, we01h[(k0) + 0], a01);                          \
            a23 = __hfma2(s0, we23h[(k0) + 0], a23);                          \
            b01 = __hfma2(s1, we01h[(k0) + 1], b01);                          \
            b23 = __hfma2(s1, we23h[(k0) + 1], b23);                          \
            a01 = __hfma2(s2, we01h[(k0) + 2], a01);                          \
            a23 = __hfma2(s2, we23h[(k0) + 2], a23);                          \
            b01 = __hfma2(s3, we01h[(k0) + 3], b01);                          \
            b23 = __hfma2(s3, we23h[(k0) + 3], b23);                          \
        }
        EE_STEP(ua, 0)
        EE_STEP(ub, 4)
        EE_STEP(uc, 8)
        EE_STEP(ud, 12)
#undef EE_STEP
        __half2 r01 = __hadd2(a01, b01);
        __half2 r23 = __hadd2(a23, b23);
        uint2 o;
        o.x = *reinterpret_cast<unsigned*>(&r01);
        o.y = *reinterpret_cast<unsigned*>(&r23);
        *(uint2*)(ee + (ebase + le) * DIM + jb) = o;   // 256B coalesced per warp
    }
}

// ---------------- fused GATv2 aggregation: TWO nodes per warp (interleaved) --
// Two independent per-edge chains double memory-level parallelism. Per-node
// edge order unchanged -> numerics identical to the 1-node version.
__device__ __forceinline__ void agg_e(
    uint2 ev, uint2 gv, u64 gr01, u64 gr23, float4 a4, bool valid,
    u64& acc01, u64& acc23, float& den)
{
    __half2 ha = *reinterpret_cast<__half2*>(&ev.x);
    __half2 hb = *reinterpret_cast<__half2*>(&ev.y);
    __half2 ga = *reinterpret_cast<__half2*>(&gv.x);
    __half2 gb = *reinterpret_cast<__half2*>(&gv.y);
    float2 ef0 = __half22float2(ha);
    float2 ef1 = __half22float2(hb);
    float2 gf0 = __half22float2(ga);
    float2 gf1 = __half22float2(gb);
    u64 ee01, ee23, g01, g23;
    PACK2(ee01, ef0.x, ef0.y);
    PACK2(ee23, ef1.x, ef1.y);
    PACK2(g01, gf0.x, gf0.y);
    PACK2(g23, gf1.x, gf1.y);
    u64 e01, e23;
    ADD2(e01, g01, gr01);
    ADD2(e23, g23, gr23);
    ADD2(e01, e01, ee01);
    ADD2(e23, e23, ee23);
    float x0, x1, x2, x3;
    UNPK2(x0, x1, e01);
    UNPK2(x2, x3, e23);
    x0 = x0 > 0.f ? x0 : 0.2f * x0;     // GATv2 leaky relu 0.2
    x1 = x1 > 0.f ? x1 : 0.2f * x1;
    x2 = x2 > 0.f ? x2 : 0.2f * x2;
    x3 = x3 > 0.f ? x3 : 0.2f * x3;
    float t = x0 * a4.x;
    t = fmaf(x1, a4.y, t);
    t = fmaf(x2, a4.z, t);
    t = fmaf(x3, a4.w, t);
    t += __shfl_xor_sync(0xffffffffu, t, 1);
    t += __shfl_xor_sync(0xffffffffu, t, 2);
    t += __shfl_xor_sync(0xffffffffu, t, 4);
    float w = valid ? __expf(t) : 0.f;
    den += w;
    u64 ww; PACK2(ww, w, w);
    FMA2(acc01, ww, g01, acc01);
    FMA2(acc23, ww, g23, acc23);
}

__global__ __launch_bounds__(256) void k_aggregate(
    const int* __restrict__ off, const int* __restrict__ srcarr,
    const __half* __restrict__ ee,
    const __half* __restrict__ glh, const float* __restrict__ gr,
    const float* __restrict__ att, const float* __restrict__ bias,
    float* __restrict__ hout, float* __restrict__ stats)
{
    __shared__ float sS[8 * DIM];
    __shared__ float sQ[8 * DIM];
    int tid = threadIdx.x;
    int lane = tid & 31;
    int wrp = tid >> 5;
    int nA = blockIdx.x * 16 + wrp * 2;   // grid exact: nA, nA+1 < N_NODES
    int nB = nA + 1;
    int jb = lane * 4;

    float4 a4 = *(const float4*)(att + jb);
    float4 b4 = *(const float4*)(bias + jb);

    ulonglong2 grvA = *(const ulonglong2*)(gr + (size_t)nA * DIM + jb);
    ulonglong2 grvB = *(const ulonglong2*)(gr + (size_t)nB * DIM + jb);
    u64 grA01 = grvA.x, grA23 = grvA.y;
    u64 grB01 = grvB.x, grB23 = grvB.y;

    int pA = off[nA];
    int endA = off[nA + 1];
    int pB = endA;                        // off[nB] == off[nA+1] (contiguous CSR)
    int endB = off[nB + 1];

    u64 accA01, accA23, accB01, accB23;
    PACK2(accA01, 0.f, 0.f);
    accA23 = accA01; accB01 = accA01; accB23 = accA01;
    float denA = 0.f, denB = 0.f;

    int m = endA - pA;
    int cB = endB - pB;
    if (cB > m) m = cB;
#pragma unroll 1
    for (int it = 0; it < m; it++) {
        bool vA = pA < endA;
        bool vB = pB < endB;
        int iA = vA ? pA : 0;
        int iB = vB ? pB : 0;
        int sA = srcarr[iA];
        int sB = srcarr[iB];
        uint2 evA = *(const uint2*)(ee + (size_t)iA * DIM + jb);   // sequential
        uint2 evB = *(const uint2*)(ee + (size_t)iB * DIM + jb);
        uint2 gvA = *(const uint2*)(glh + (size_t)sA * DIM + jb);  // L2 gather
        uint2 gvB = *(const uint2*)(glh + (size_t)sB * DIM + jb);
        agg_e(evA, gvA, grA01, grA23, a4, vA, accA01, accA23, denA);
        agg_e(evB, gvB, grB01, grB23, a4, vB, accB01, accB23, denB);
        pA += vA;
        pB += vB;
    }

    float rdenA = 1.0f / (denA + 1e-16f);
    float rdenB = 1.0f / (denB + 1e-16f);
    float aA0, aA1, aA2, aA3, aB0, aB1, aB2, aB3;
    UNPK2(aA0, aA1, accA01);
    UNPK2(aA2, aA3, accA23);
    UNPK2(aB0, aB1, accB01);
    UNPK2(aB2, aB3, accB23);
    float oA0 = aA0 * rdenA + b4.x;
    float oA1 = aA1 * rdenA + b4.y;
    float oA2 = aA2 * rdenA + b4.z;
    float oA3 = aA3 * rdenA + b4.w;
    float oB0 = aB0 * rdenB + b4.x;
    float oB1 = aB1 * rdenB + b4.y;
    float oB2 = aB2 * rdenB + b4.z;
    float oB3 = aB3 * rdenB + b4.w;
    *(float4*)(hout + (size_t)nA * DIM + jb) = make_float4(oA0, oA1, oA2, oA3);
    *(float4*)(hout + (size_t)nB * DIM + jb) = make_float4(oB0, oB1, oB2, oB3);

    // BN partials: per-warp disjoint smem slices (2-node sums), no smem atomics
    int base = wrp * DIM + jb;
    sS[base + 0] = oA0 + oB0;  sQ[base + 0] = oA0 * oA0 + oB0 * oB0;
    sS[base + 1] = oA1 + oB1;  sQ[base + 1] = oA1 * oA1 + oB1 * oB1;
    sS[base + 2] = oA2 + oB2;  sQ[base + 2] = oA2 * oA2 + oB2 * oB2;
    sS[base + 3] = oA3 + oB3;  sQ[base + 3] = oA3 * oA3 + oB3 * oB3;
    __syncthreads();
    if (tid < DIM) {
        float s = 0.f, q = 0.f;
#pragma unroll
        for (int w = 0; w < 8; w++) {
            s += sS[w * DIM + tid];
            q += sQ[w * DIM + tid];
        }
        atomicAdd(&stats[tid], s);
        atomicAdd(&stats[DIM + tid], q);
    }
}

// ---------------- BN stats finalize (and reset accumulators) ----------------
__global__ void k_bn_finalize(float* __restrict__ stats,
                              const float* __restrict__ gamma,
                              const float* __restrict__ beta,
                              float* __restrict__ bnp)
{
    int j = threadIdx.x;
    float inv_n = 1.0f / (float)N_NODES;
    float mu = stats[j] * inv_n;
    float var = stats[DIM + j] * inv_n - mu * mu;
    float rs = rsqrtf(var + 1e-5f);
    float sc = rs * gamma[j];
    bnp[j] = sc;
    bnp[DIM + j] = beta[j] - mu * sc;
    stats[j] = 0.f;
    stats[DIM + j] = 0.f;
}

// ---------------- launch ----------------
extern "C" void kernel_launch(void* const* d_in, const int* in_sizes, int n_in,
                              void* d_out, int out_size)
{
    const float* x    = (const float*)d_in[0];
    const int*   ei   = (const int*)d_in[1];     // int32
    const float* ea   = (const float*)d_in[2];
    const float* Wl   = (const float*)d_in[3];
    const float* bl   = (const float*)d_in[4];
    const float* Wr   = (const float*)d_in[5];
    const float* br   = (const float*)d_in[6];
    const float* We   = (const float*)d_in[7];
    const float* att  = (const float*)d_in[8];
    const float* bias = (const float*)d_in[9];
    const float* gamma= (const float*)d_in[10];
    const float* beta = (const float*)d_in[11];
    const float* Wf   = (const float*)d_in[12];
    const float* bf   = (const float*)d_in[13];
    float* out = (float*)d_out;

    float *p_h, *p_gr, *p_stats, *p_bnp;
    unsigned *p_eacsr;
    __half *p_ee, *p_glh;
    int *p_cnt, *p_off, *p_cur, *p_bsum, *p_src, *p_epos;
    cudaGetSymbolAddress((void**)&p_h,     g_h);
    cudaGetSymbolAddress((void**)&p_glh,   g_glh);
    cudaGetSymbolAddress((void**)&p_gr,    g_gr);
    cudaGetSymbolAddress((void**)&p_eacsr, g_eacsr);
    cudaGetSymbolAddress((void**)&p_ee,    g_ee);
    cudaGetSymbolAddress((void**)&p_stats, g_stats);
    cudaGetSymbolAddress((void**)&p_bnp,   g_bnp);
    cudaGetSymbolAddress((void**)&p_cnt,   g_cnt);
    cudaGetSymbolAddress((void**)&p_off,   g_off);
    cudaGetSymbolAddress((void**)&p_cur,   g_cursor);
    cudaGetSymbolAddress((void**)&p_bsum,  g_bsum);
    cudaGetSymbolAddress((void**)&p_src,   g_srcarr);
    cudaGetSymbolAddress((void**)&p_epos,  g_epos);

    int gemm_blocks = N_NODES / 16;            // 6250 (exact)
    int agg_blocks  = N_NODES / 16;            // 6250 (2 nodes/warp x 8 warps)
    int ee_blocks   = N_EDGES / 256;           // 6250

    // launch #4 = k_gemm_dual (ncu capture slot)
    k_hist<<<(N_EDGES + 255) / 256, 256>>>(ei, p_cnt);                   // 1
    k_scan1<<<NBLK, 1024>>>(p_cnt, p_off, p_bsum);                       // 2
    k_scan23<<<(N_NODES + 255) / 256, 256>>>(p_off, p_bsum, p_cur);      // 3
    k_gemm_dual<<<gemm_blocks, 128>>>(x, 0, p_bnp, Wl, bl, Wr, br,
                                      p_glh, p_gr);                      // 4 (profiled)
    k_scatter<<<(N_EDGES + 255) / 256, 256>>>(ei, p_cur, p_src, p_epos); // 5
    k_permute<<<N_EDGES / 256, 256>>>(ea, p_epos, p_eacsr);              // 6 (once)

    for (int L = 0; L < 3; L++) {
        if (L > 0) {
            k_gemm_dual<<<gemm_blocks, 128>>>(p_h, 1, p_bnp,
                                              Wl + L * DIM * DIM, bl + L * DIM,
                                              Wr + L * DIM * DIM, br + L * DIM,
                                              p_glh, p_gr);
        }
        k_ee<<<ee_blocks, 256>>>(p_eacsr, We + L * EDIM * DIM, p_ee);
        k_aggregate<<<agg_blocks, 256>>>(p_off, p_src, p_ee, p_glh, p_gr,
                                         att + L * DIM, bias + L * DIM,
                                         p_h, p_stats);
        k_bn_finalize<<<1, 128>>>(p_stats, gamma + L * DIM, beta + L * DIM, p_bnp);
    }
    k_gemm_final<<<gemm_blocks, 128>>>(p_h, p_bnp, Wf, bf, out);
}